// round 5
// baseline (speedup 1.0000x reference)
#include <cuda_runtime.h>

#define N_CAMS 5
#define BATCH  4
#define NJ     15
#define HH     128
#define WW     240
#define CX     80
#define CY     80
#define CZ     20
#define NBINS  (CX*CY*CZ)      /* 128000 */
#define HW     (HH*WW)         /* 30720  */
#define JP     16              /* J padded to 16 for float4 vector taps */
#define PRMX   28              /* packed floats per (cam,b), 16B-aligned */

// Scratch: transposed heatmaps, J-last padded to 16 (64B-aligned tap vectors).
// ~39.3 MB device global (allocation-free scratch per harness rules).
__device__ float g_hmT[(size_t)N_CAMS * BATCH * HW * JP];
// Packed per-(cam,batch) params:
//  0-8 R, 9-11 T, 12 fx, 13 fy, 14 cx, 15 cy, 16-18 k, 19 p0, 20 p1,
//  21 w, 22 h, 23 pad, 24 2/(w-1), 25 2/(h-1), 26-27 pad
__device__ float g_prm[N_CAMS * BATCH * PRMX];

// ---------------------------------------------------------------------------
// Kernel 1: pack camera params into an aligned 28-float struct per (cam,b).
// ---------------------------------------------------------------------------
__global__ void prep_params(const float* __restrict__ R, const float* __restrict__ T,
                            const float* __restrict__ f, const float* __restrict__ c,
                            const float* __restrict__ k, const float* __restrict__ p,
                            const float* __restrict__ wh) {
    int t = blockIdx.x * blockDim.x + threadIdx.x;
    if (t >= N_CAMS * BATCH * PRMX) return;
    int cbi = t / PRMX, s = t % PRMX;
    float v = 0.f;
    if      (s <  9) v = R [cbi * 9 + s];
    else if (s < 12) v = T [cbi * 3 + (s - 9)];
    else if (s < 14) v = f [cbi * 2 + (s - 12)];
    else if (s < 16) v = c [cbi * 2 + (s - 14)];
    else if (s < 19) v = k [cbi * 3 + (s - 16)];
    else if (s < 21) v = p [cbi * 2 + (s - 19)];
    else if (s < 23) v = wh[cbi * 2 + (s - 21)];
    else if (s == 24) v = 2.0f / (wh[cbi * 2 + 0] - 1.0f);
    else if (s == 25) v = 2.0f / (wh[cbi * 2 + 1] - 1.0f);
    g_prm[t] = v;
}

// ---------------------------------------------------------------------------
// Kernel 2: transpose heatmaps [cb][J][H*W] -> [cb][H*W][16] via smem tile.
// Block = 256 threads = 16 joints x 16 pixels. Conflict-free (stride-17 tile).
// Output stores are fully coalesced (1KB contiguous per block).
// ---------------------------------------------------------------------------
__global__ void transpose_hm(const float* __restrict__ hm) {
    __shared__ float tile[16][17];
    const int nb = HW / 16;                 // 1920 pixel-tiles per (cam,b)
    int cb = blockIdx.x / nb;
    int p0 = (blockIdx.x % nb) * 16;
    int tid = threadIdx.x;
    int jr = tid >> 4, xr = tid & 15;
    float v = 0.f;
    if (jr < NJ)
        v = hm[((size_t)cb * NJ + jr) * HW + p0 + xr];
    tile[jr][xr] = v;                       // pad joint 15 -> 0
    __syncthreads();
    int px = tid >> 4, jc = tid & 15;
    g_hmT[((size_t)cb * HW + p0 + px) * JP + jc] = tile[jc][px];
}

// ---------------------------------------------------------------------------
// Kernel 3: one thread per (b, voxel). 5 camera projections; per valid cam,
// 4 bilinear taps, each a 64B J-vector read as 4x float4; accumulate 15 joints.
// Per-cam params staged in shared memory once per block.
// ---------------------------------------------------------------------------
__global__ void __launch_bounds__(256) voxel_kernel(
    const float* __restrict__ gctr, const float* __restrict__ gsz,
    float* __restrict__ out_cubes, float* __restrict__ out_grids, int write_grids)
{
    __shared__ float sprm[N_CAMS * PRMX];   // this block's batch only

    int t = blockIdx.x * 256 + threadIdx.x;     // grid sized exactly B*NBINS
    int b = t / NBINS;                          // constant within a block (NBINS%256==0)
    int m = t - b * NBINS;

    // Cooperative param stage: 5 cams * 28 floats = 140 floats (broadcast reads later).
    if (threadIdx.x < N_CAMS * PRMX) {
        int n = threadIdx.x / PRMX, s = threadIdx.x % PRMX;
        sprm[threadIdx.x] = g_prm[(n * BATCH + b) * PRMX + s];
    }
    __syncthreads();

    int iz  = m % CZ;
    int ixy = m / CZ;
    int iy  = ixy % CY;
    int ix  = ixy / CY;

    float gs0 = __ldg(gsz),     gs1 = __ldg(gsz + 1), gs2 = __ldg(gsz + 2);
    float c0  = __ldg(gctr + b * 3), c1 = __ldg(gctr + b * 3 + 1), c2 = __ldg(gctr + b * 3 + 2);
    // linspace(-gs/2, gs/2, C) + center   (mul then add, like XLA)
    float gx = (__fadd_rn(-0.5f * gs0, __fmul_rn((float)ix, gs0 / (float)(CX - 1)))) + c0;
    float gy = (__fadd_rn(-0.5f * gs1, __fmul_rn((float)iy, gs1 / (float)(CY - 1)))) + c1;
    float gz = (__fadd_rn(-0.5f * gs2, __fmul_rn((float)iz, gs2 / (float)(CZ - 1)))) + c2;

    if (write_grids) {
        float* gp = out_grids + ((size_t)b * NBINS + m) * 3;
        gp[0] = gx; gp[1] = gy; gp[2] = gz;
    }

    float acc[JP];
    #pragma unroll
    for (int j = 0; j < JP; j++) acc[j] = 0.f;
    float den = 0.f;

    #pragma unroll
    for (int n = 0; n < N_CAMS; n++) {
        const float* q = sprm + n * PRMX;
        float dx = gx - q[9], dy = gy - q[10], dz = gz - q[11];
        float xc = q[0] * dx + q[1] * dy + q[2] * dz;
        float yc = q[3] * dx + q[4] * dy + q[5] * dz;
        float zc = q[6] * dx + q[7] * dy + q[8] * dz;
        float iv = 1.0f / zc;
        float y0v = xc * iv, y1v = yc * iv;
        float r2 = y0v * y0v + y1v * y1v;
        float radial = 1.0f + q[16] * r2 + q[17] * r2 * r2 + q[18] * r2 * r2 * r2;
        float tang = q[19] * y1v + q[20] * y0v;   // p0*y1 + p1*y0
        float rt = radial + tang;
        float sx = y0v * rt + r2 * q[20];          // + r2*p1
        float sy = y1v * rt + r2 * q[19];          // + r2*p0
        float px = sx * q[12] + q[14];
        float py = sy * q[13] + q[15];
        float w_ = q[21], h_ = q[22];

        if (!(px >= 0.f && py >= 0.f && px < w_ && py < h_)) continue;
        den += 1.0f;

        // Inside bound: px in [0,w), py in [0,h) -> outer clips are identities.
        float nx = fminf(px * q[24] - 1.0f, 1.1f);
        float ny = fminf(py * q[25] - 1.0f, 1.1f);
        float fx_ = (nx + 1.f) * 0.5f * (float)(WW - 1);
        float fy_ = (ny + 1.f) * 0.5f * (float)(HH - 1);
        float x0f = floorf(fx_), y0f = floorf(fy_);
        float wx1 = fx_ - x0f,  wy1 = fy_ - y0f;
        float wx0 = 1.f - wx1,  wy0 = 1.f - wy1;
        int x0  = min((int)x0f, WW - 1);          // x0f >= 0 inside bound
        int y0i = min((int)y0f, HH - 1);
        bool vx1 = (x0f + 1.f) < (float)WW;       // per-tap validity (ref semantics)
        bool vy1 = (y0f + 1.f) < (float)HH;

        float w00 = wx0 * wy0, w01 = wx1 * wy0, w10 = wx0 * wy1, w11 = wx1 * wy1;
        if (!vx1) { w01 = 0.f; w11 = 0.f; }
        if (!vy1) { w10 = 0.f; w11 = 0.f; }
        int x1  = vx1 ? x0 + 1 : x0;
        int y1i = vy1 ? y0i + 1 : y0i;

        const float* basep = g_hmT + (size_t)(n * BATCH + b) * HW * JP;
        const float4* p00 = (const float4*)(basep + ((size_t)y0i * WW + x0) * JP);
        const float4* p01 = (const float4*)(basep + ((size_t)y0i * WW + x1) * JP);
        const float4* p10 = (const float4*)(basep + ((size_t)y1i * WW + x0) * JP);
        const float4* p11 = (const float4*)(basep + ((size_t)y1i * WW + x1) * JP);

        // Issue all 16 tap loads up front (16-wide MLP), then accumulate.
        float4 a0 = __ldg(p00 + 0), a1 = __ldg(p00 + 1), a2 = __ldg(p00 + 2), a3 = __ldg(p00 + 3);
        float4 e0 = __ldg(p01 + 0), e1 = __ldg(p01 + 1), e2 = __ldg(p01 + 2), e3 = __ldg(p01 + 3);
        float4 g0 = __ldg(p10 + 0), g1 = __ldg(p10 + 1), g2 = __ldg(p10 + 2), g3 = __ldg(p10 + 3);
        float4 d0 = __ldg(p11 + 0), d1 = __ldg(p11 + 1), d2 = __ldg(p11 + 2), d3 = __ldg(p11 + 3);

        #define ACC4(qq, A, E, G, D)                                   \
            acc[qq*4+0] += w00 * A.x + w01 * E.x + w10 * G.x + w11 * D.x; \
            acc[qq*4+1] += w00 * A.y + w01 * E.y + w10 * G.y + w11 * D.y; \
            acc[qq*4+2] += w00 * A.z + w01 * E.z + w10 * G.z + w11 * D.z; \
            acc[qq*4+3] += w00 * A.w + w01 * E.w + w10 * G.w + w11 * D.w;
        ACC4(0, a0, e0, g0, d0)
        ACC4(1, a1, e1, g1, d1)
        ACC4(2, a2, e2, g2, d2)
        ACC4(3, a3, e3, g3, d3)
        #undef ACC4
    }

    float invd = 1.0f / (den + 1e-6f);
    #pragma unroll
    for (int j = 0; j < NJ; j++) {
        float v = acc[j] * invd;
        v = fminf(fmaxf(v, 0.f), 1.f);
        out_cubes[((size_t)b * NJ + j) * NBINS + m] = v;
    }
}

// ---------------------------------------------------------------------------
extern "C" void kernel_launch(void* const* d_in, const int* in_sizes, int n_in,
                              void* d_out, int out_size) {
    const float* hm   = (const float*)d_in[0];
    const float* R    = (const float*)d_in[1];
    const float* T    = (const float*)d_in[2];
    const float* f    = (const float*)d_in[3];
    const float* c    = (const float*)d_in[4];
    const float* k    = (const float*)d_in[5];
    const float* p    = (const float*)d_in[6];
    const float* wh   = (const float*)d_in[7];
    const float* gctr = (const float*)d_in[8];
    const float* gsz  = (const float*)d_in[9];

    float* out = (float*)d_out;
    const int cubes_n = BATCH * NJ * NBINS;      // 7,680,000
    const int grids_n = BATCH * NBINS * 3;       // 1,536,000
    int write_grids = (out_size >= cubes_n + grids_n) ? 1 : 0;
    float* out_grids = out + cubes_n;

    prep_params<<<2, 512>>>(R, T, f, c, k, p, wh);
    transpose_hm<<<N_CAMS * BATCH * (HW / 16), 256>>>(hm);
    voxel_kernel<<<(BATCH * NBINS) / 256, 256>>>(gctr, gsz, out, out_grids, write_grids);
}

// round 11
// speedup vs baseline: 1.7026x; 1.7026x over previous
#include <cuda_runtime.h>
#include <cuda_fp16.h>

#define N_CAMS 5
#define BATCH  4
#define NJ     15
#define HH     128
#define WW     240
#define CX     80
#define CY     80
#define CZ     20
#define NBINS  (CX*CY*CZ)      /* 128000 */
#define HW     (HH*WW)         /* 30720  */
#define JP     16              /* J padded to 16 -> 32B half vector per pixel */
#define PRMX   28              /* packed floats per (cam,b) in smem */

// Scratch: transposed heatmaps, J-last padded to 16, fp16. ~19.7 MB.
__device__ __half g_hmT[(size_t)N_CAMS * BATCH * HW * JP];

// ---------------------------------------------------------------------------
// Kernel 1: transpose+convert heatmaps [cb][J][H*W] f32 -> [cb][H*W][16] f16.
// Block = 256 threads, one 16x16 (joint x pixel) tile. Store phase: 128
// threads write half2 (joint pairs) -> 512B contiguous per block.
// ---------------------------------------------------------------------------
__global__ void transpose_hm(const float* __restrict__ hm) {
    __shared__ float tile[16][17];
    const int nb = HW / 16;                 // 1920 pixel-tiles per (cam,b)
    int cb = blockIdx.x / nb;
    int p0 = (blockIdx.x % nb) * 16;
    int tid = threadIdx.x;
    int jr = tid >> 4, xr = tid & 15;
    float v = 0.f;
    if (jr < NJ)
        v = hm[((size_t)cb * NJ + jr) * HW + p0 + xr];
    tile[jr][xr] = v;                       // pad joint 15 -> 0
    __syncthreads();
    if (tid < 128) {
        int px = tid >> 3, jp = tid & 7;    // pixel 0..15, joint-pair 0..7
        __half2 h = __floats2half2_rn(tile[2 * jp][px], tile[2 * jp + 1][px]);
        ((__half2*)g_hmT)[((size_t)cb * HW + p0 + px) * 8 + jp] = h;
    }
}

// ---------------------------------------------------------------------------
// Kernel 2: one thread per (b, voxel). Param packing fused into per-block
// smem staging. Per valid cam: 4 bilinear taps, each a 32B fp16 J-vector
// read as 2x uint4 (2 LDG.128); fp32 accumulate over 15 joints.
// ---------------------------------------------------------------------------
__global__ void __launch_bounds__(256) voxel_kernel(
    const float* __restrict__ R, const float* __restrict__ T,
    const float* __restrict__ f, const float* __restrict__ c,
    const float* __restrict__ k, const float* __restrict__ p,
    const float* __restrict__ wh,
    const float* __restrict__ gctr, const float* __restrict__ gsz,
    float* __restrict__ out_cubes, float* __restrict__ out_grids, int write_grids)
{
    __shared__ float sprm[N_CAMS * PRMX];   // this block's batch only

    int t = blockIdx.x * 256 + threadIdx.x;     // grid sized exactly B*NBINS
    int b = t / NBINS;                          // constant within a block (NBINS%256==0)
    int m = t - b * NBINS;

    // Fused param packing: 5 cams * 28 floats = 140 staged values.
    //  0-8 R, 9-11 T, 12 fx, 13 fy, 14 cx, 15 cy, 16-18 k, 19 p0, 20 p1,
    //  21 w, 22 h, 23 pad, 24 2/(w-1), 25 2/(h-1), 26-27 pad
    if (threadIdx.x < N_CAMS * PRMX) {
        int n = threadIdx.x / PRMX, s = threadIdx.x % PRMX;
        int cbi = n * BATCH + b;
        float v = 0.f;
        if      (s <  9) v = R [cbi * 9 + s];
        else if (s < 12) v = T [cbi * 3 + (s - 9)];
        else if (s < 14) v = f [cbi * 2 + (s - 12)];
        else if (s < 16) v = c [cbi * 2 + (s - 14)];
        else if (s < 19) v = k [cbi * 3 + (s - 16)];
        else if (s < 21) v = p [cbi * 2 + (s - 19)];
        else if (s < 23) v = wh[cbi * 2 + (s - 21)];
        else if (s == 24) v = 2.0f / (wh[cbi * 2 + 0] - 1.0f);
        else if (s == 25) v = 2.0f / (wh[cbi * 2 + 1] - 1.0f);
        sprm[threadIdx.x] = v;
    }
    __syncthreads();

    int iz  = m % CZ;
    int ixy = m / CZ;
    int iy  = ixy % CY;
    int ix  = ixy / CY;

    float gs0 = __ldg(gsz),     gs1 = __ldg(gsz + 1), gs2 = __ldg(gsz + 2);
    float c0  = __ldg(gctr + b * 3), c1 = __ldg(gctr + b * 3 + 1), c2 = __ldg(gctr + b * 3 + 2);
    // linspace(-gs/2, gs/2, C) + center   (mul then add, like XLA)
    float gx = (__fadd_rn(-0.5f * gs0, __fmul_rn((float)ix, gs0 / (float)(CX - 1)))) + c0;
    float gy = (__fadd_rn(-0.5f * gs1, __fmul_rn((float)iy, gs1 / (float)(CY - 1)))) + c1;
    float gz = (__fadd_rn(-0.5f * gs2, __fmul_rn((float)iz, gs2 / (float)(CZ - 1)))) + c2;

    if (write_grids) {
        float* gp = out_grids + ((size_t)b * NBINS + m) * 3;
        gp[0] = gx; gp[1] = gy; gp[2] = gz;
    }

    float acc[JP];
    #pragma unroll
    for (int j = 0; j < JP; j++) acc[j] = 0.f;
    float den = 0.f;

    #pragma unroll
    for (int n = 0; n < N_CAMS; n++) {
        const float* q = sprm + n * PRMX;
        float dx = gx - q[9], dy = gy - q[10], dz = gz - q[11];
        float xc = q[0] * dx + q[1] * dy + q[2] * dz;
        float yc = q[3] * dx + q[4] * dy + q[5] * dz;
        float zc = q[6] * dx + q[7] * dy + q[8] * dz;
        float iv = 1.0f / zc;
        float y0v = xc * iv, y1v = yc * iv;
        float r2 = y0v * y0v + y1v * y1v;
        float radial = 1.0f + q[16] * r2 + q[17] * r2 * r2 + q[18] * r2 * r2 * r2;
        float tang = q[19] * y1v + q[20] * y0v;   // p0*y1 + p1*y0
        float rt = radial + tang;
        float sx = y0v * rt + r2 * q[20];          // + r2*p1
        float sy = y1v * rt + r2 * q[19];          // + r2*p0
        float px = sx * q[12] + q[14];
        float py = sy * q[13] + q[15];
        float w_ = q[21], h_ = q[22];

        if (!(px >= 0.f && py >= 0.f && px < w_ && py < h_)) continue;
        den += 1.0f;

        // Inside bound: px in [0,w), py in [0,h) -> outer clips are identities.
        float nx = fminf(px * q[24] - 1.0f, 1.1f);
        float ny = fminf(py * q[25] - 1.0f, 1.1f);
        float fx_ = (nx + 1.f) * 0.5f * (float)(WW - 1);
        float fy_ = (ny + 1.f) * 0.5f * (float)(HH - 1);
        float x0f = floorf(fx_), y0f = floorf(fy_);
        float wx1 = fx_ - x0f,  wy1 = fy_ - y0f;
        float wx0 = 1.f - wx1,  wy0 = 1.f - wy1;
        int x0  = min((int)x0f, WW - 1);          // x0f >= 0 inside bound
        int y0i = min((int)y0f, HH - 1);
        bool vx1 = (x0f + 1.f) < (float)WW;       // per-tap validity (ref semantics)
        bool vy1 = (y0f + 1.f) < (float)HH;

        float w00 = wx0 * wy0, w01 = wx1 * wy0, w10 = wx0 * wy1, w11 = wx1 * wy1;
        if (!vx1) { w01 = 0.f; w11 = 0.f; }
        if (!vy1) { w10 = 0.f; w11 = 0.f; }
        int x1  = vx1 ? x0 + 1 : x0;
        int y1i = vy1 ? y0i + 1 : y0i;

        const __half* basep = g_hmT + (size_t)(n * BATCH + b) * HW * JP;
        const uint4* p00 = (const uint4*)(basep + ((size_t)y0i * WW + x0) * JP);
        const uint4* p01 = (const uint4*)(basep + ((size_t)y0i * WW + x1) * JP);
        const uint4* p10 = (const uint4*)(basep + ((size_t)y1i * WW + x0) * JP);
        const uint4* p11 = (const uint4*)(basep + ((size_t)y1i * WW + x1) * JP);

        // 8 LDG.128 per cam (was 16 in fp32). Issue all, then accumulate.
        uint4 a0 = __ldg(p00 + 0), a1 = __ldg(p00 + 1);
        uint4 e0 = __ldg(p01 + 0), e1 = __ldg(p01 + 1);
        uint4 g0 = __ldg(p10 + 0), g1 = __ldg(p10 + 1);
        uint4 d0 = __ldg(p11 + 0), d1 = __ldg(p11 + 1);

        // Each uint4 = 8 halves = 4 half2 (joint pairs).
        #define ACC8(off, A, E, G, D) {                                       \
            const __half2* Ah = (const __half2*)&A;                            \
            const __half2* Eh = (const __half2*)&E;                            \
            const __half2* Gh = (const __half2*)&G;                            \
            const __half2* Dh = (const __half2*)&D;                            \
            _Pragma("unroll")                                                  \
            for (int kk = 0; kk < 4; kk++) {                                   \
                float2 fa = __half22float2(Ah[kk]);                            \
                float2 fe = __half22float2(Eh[kk]);                            \
                float2 fg = __half22float2(Gh[kk]);                            \
                float2 fd = __half22float2(Dh[kk]);                            \
                acc[off + 2*kk + 0] += w00*fa.x + w01*fe.x + w10*fg.x + w11*fd.x; \
                acc[off + 2*kk + 1] += w00*fa.y + w01*fe.y + w10*fg.y + w11*fd.y; \
            }                                                                  \
        }
        ACC8(0, a0, e0, g0, d0)
        ACC8(8, a1, e1, g1, d1)
        #undef ACC8
    }

    float invd = 1.0f / (den + 1e-6f);
    #pragma unroll
    for (int j = 0; j < NJ; j++) {
        float v = acc[j] * invd;
        v = fminf(fmaxf(v, 0.f), 1.f);
        out_cubes[((size_t)b * NJ + j) * NBINS + m] = v;
    }
}

// ---------------------------------------------------------------------------
extern "C" void kernel_launch(void* const* d_in, const int* in_sizes, int n_in,
                              void* d_out, int out_size) {
    const float* hm   = (const float*)d_in[0];
    const float* R    = (const float*)d_in[1];
    const float* T    = (const float*)d_in[2];
    const float* f    = (const float*)d_in[3];
    const float* c    = (const float*)d_in[4];
    const float* k    = (const float*)d_in[5];
    const float* p    = (const float*)d_in[6];
    const float* wh   = (const float*)d_in[7];
    const float* gctr = (const float*)d_in[8];
    const float* gsz  = (const float*)d_in[9];

    float* out = (float*)d_out;
    const int cubes_n = BATCH * NJ * NBINS;      // 7,680,000
    const int grids_n = BATCH * NBINS * 3;       // 1,536,000
    int write_grids = (out_size >= cubes_n + grids_n) ? 1 : 0;
    float* out_grids = out + cubes_n;

    transpose_hm<<<N_CAMS * BATCH * (HW / 16), 256>>>(hm);
    voxel_kernel<<<(BATCH * NBINS) / 256, 256>>>(R, T, f, c, k, p, wh,
                                                 gctr, gsz, out, out_grids, write_grids);
}